// round 4
// baseline (speedup 1.0000x reference)
#include <cuda_runtime.h>
#include <math.h>

#define W_   640
#define H_   480
#define HW_  (W_ * H_)
#define CIN  14
#define COUT 15
#define TPB  256

struct ViewConst {
    float M[9];   // inv(intrinsics)
    float R[9];   // extrinsics rotation
    float t[3];   // extrinsics translation
    float mult;   // sum(inv(intr[:2,:2]))
};
__device__ ViewConst g_views[16];

__global__ void prep_kernel(const float* __restrict__ ext,
                            const float* __restrict__ intr, int v) {
    int i = blockIdx.x * blockDim.x + threadIdx.x;
    if (i >= v) return;
    const float* K = intr + i * 9;
    float a = K[0], b = K[1], c = K[2];
    float d = K[3], e = K[4], f = K[5];
    float g = K[6], h = K[7], k = K[8];
    float A = e * k - f * h;
    float B = f * g - d * k;
    float C = d * h - e * g;
    float det = a * A + b * B + c * C;
    float inv = 1.0f / det;
    ViewConst vc;
    vc.M[0] = A * inv;           vc.M[1] = (c * h - b * k) * inv; vc.M[2] = (b * f - c * e) * inv;
    vc.M[3] = B * inv;           vc.M[4] = (a * k - c * g) * inv; vc.M[5] = (c * d - a * f) * inv;
    vc.M[6] = C * inv;           vc.M[7] = (b * g - a * h) * inv; vc.M[8] = (a * e - b * d) * inv;
    const float* E = ext + i * 16;
    for (int r = 0; r < 3; r++) {
        vc.R[r * 3 + 0] = E[r * 4 + 0];
        vc.R[r * 3 + 1] = E[r * 4 + 1];
        vc.R[r * 3 + 2] = E[r * 4 + 2];
        vc.t[r]         = E[r * 4 + 3];
    }
    float det2 = a * e - b * d;
    vc.mult = (a + e - b - d) / det2;   // sum of 2x2 inverse entries
    g_views[i] = vc;
}

__device__ __forceinline__ float sigmoidf_(float x) {
    return __fdividef(1.0f, 1.0f + expf(-x));
}
__device__ __forceinline__ float softplusf_(float x) {
    // stable log(1+exp(x))
    return x > 0.0f ? x + log1pf(expf(-x)) : log1pf(expf(x));
}

__global__ __launch_bounds__(TPB) void splat_kernel(const float* __restrict__ raw,
                                                    float* __restrict__ out) {
    __shared__ float s[TPB * COUT];

    int p   = blockIdx.x * TPB + threadIdx.x;   // HW_ % TPB == 0 -> no view straddle
    int vi  = p / HW_;
    int pix = p - vi * HW_;
    int y   = pix / W_;
    int x   = pix - y * W_;

    const float* base = raw + (size_t)vi * CIN * HW_ + pix;
    float ch[CIN];
#pragma unroll
    for (int c = 0; c < CIN; c++) ch[c] = __ldg(base + (size_t)c * HW_);

    const ViewConst& vc = g_views[vi];

    // pixel coords + sigmoid offset, unproject through inv(K)
    float cx = (float)x + sigmoidf_(ch[12]) - 0.5f;
    float cy = (float)y + sigmoidf_(ch[13]) - 0.5f;
    float dx = vc.M[0] * cx + vc.M[1] * cy + vc.M[2];
    float dy = vc.M[3] * cx + vc.M[4] * cy + vc.M[5];
    float dz = vc.M[6] * cx + vc.M[7] * cy + vc.M[8];
    float dn = rsqrtf(dx * dx + dy * dy + dz * dz);
    dx *= dn; dy *= dn; dz *= dn;

    // rotate to world (homogeneous w=0 -> rotation only)
    float wdx = vc.R[0] * dx + vc.R[1] * dy + vc.R[2] * dz;
    float wdy = vc.R[3] * dx + vc.R[4] * dy + vc.R[5] * dz;
    float wdz = vc.R[6] * dx + vc.R[7] * dy + vc.R[8] * dz;

    float disp  = sigmoidf_(ch[3]);
    float depth = __fdividef(1.0f, disp * (1.0f / 0.05f - 1.0f / 20.0f) + 1.0f / 20.0f);

    float mx = vc.t[0] + wdx * depth;
    float my = vc.t[1] + wdy * depth;
    float mz = vc.t[2] + wdz * depth;

    // quaternion (x,y,z,w) -> rotation matrix
    float qx = ch[8], qy = ch[9], qz = ch[10], qw = ch[11];
    float qn = rsqrtf(qx * qx + qy * qy + qz * qz + qw * qw);
    qx *= qn; qy *= qn; qz *= qn; qw *= qn;

    float c00 = 1.0f - 2.0f * (qy * qy + qz * qz);
    float c01 = 2.0f * (qx * qy - qz * qw);
    float c02 = 2.0f * (qx * qz + qy * qw);
    float c10 = 2.0f * (qx * qy + qz * qw);
    float c11 = 1.0f - 2.0f * (qx * qx + qz * qz);
    float c12 = 2.0f * (qy * qz - qx * qw);
    float c20 = 2.0f * (qx * qz - qy * qw);
    float c21 = 2.0f * (qy * qz + qx * qw);
    float c22 = 1.0f - 2.0f * (qx * qx + qy * qy);

    // m = R_ext * cam_m
    float m00 = vc.R[0] * c00 + vc.R[1] * c10 + vc.R[2] * c20;
    float m01 = vc.R[0] * c01 + vc.R[1] * c11 + vc.R[2] * c21;
    float m02 = vc.R[0] * c02 + vc.R[1] * c12 + vc.R[2] * c22;
    float m10 = vc.R[3] * c00 + vc.R[4] * c10 + vc.R[5] * c20;
    float m11 = vc.R[3] * c01 + vc.R[4] * c11 + vc.R[5] * c21;
    float m12 = vc.R[3] * c02 + vc.R[4] * c12 + vc.R[5] * c22;
    float m20 = vc.R[6] * c00 + vc.R[7] * c10 + vc.R[8] * c20;
    float m21 = vc.R[6] * c01 + vc.R[7] * c11 + vc.R[8] * c21;
    float m22 = vc.R[6] * c02 + vc.R[7] * c12 + vc.R[8] * c22;

    float tr = m00 + m11 + m22;
    // argmax([m00,m11,m22,tr]) with first-occurrence tie rule
    int choice = 0; float best = m00;
    if (m11 > best) { best = m11; choice = 1; }
    if (m22 > best) { best = m22; choice = 2; }
    if (tr  > best) {             choice = 3; }

    float q0, q1, q2, q3;
    if (choice == 0)      { q0 = m21 - m12; q1 = 1.0f + m00 - m11 - m22; q2 = m01 + m10; q3 = m02 + m20; }
    else if (choice == 1) { q0 = m02 - m20; q1 = m01 + m10; q2 = 1.0f + m11 - m00 - m22; q3 = m12 + m21; }
    else if (choice == 2) { q0 = m10 - m01; q1 = m02 + m20; q2 = m12 + m21; q3 = 1.0f + m22 - m00 - m11; }
    else                  { q0 = 1.0f + tr; q1 = m21 - m12; q2 = m02 - m20; q3 = m10 - m01; }
    float qrn = rsqrtf(q0 * q0 + q1 * q1 + q2 * q2 + q3 * q3);
    q0 *= qrn; q1 *= qrn; q2 *= qrn; q3 *= qrn;

    // stage 15 channels/pixel in smem (stride 15 is odd -> conflict-free)
    float* sp = s + threadIdx.x * COUT;
    sp[0]  = mx; sp[1] = my; sp[2] = mz; sp[3] = 1.0f;
    sp[4]  = softplusf_(ch[0]);
    sp[5]  = softplusf_(ch[1]);
    sp[6]  = softplusf_(ch[2]);
    sp[7]  = sigmoidf_(ch[4]);
    sp[8]  = softplusf_(ch[5]) * vc.mult;
    sp[9]  = softplusf_(ch[6]) * vc.mult;
    sp[10] = softplusf_(ch[7]) * vc.mult;
    sp[11] = q0; sp[12] = q1; sp[13] = q2; sp[14] = q3;
    __syncthreads();

    // coalesced 16B-vector writeback: 256*15*4 = 15360 bytes, 16B aligned per block
    float4*       o4 = reinterpret_cast<float4*>(out + (size_t)blockIdx.x * TPB * COUT);
    const float4* s4 = reinterpret_cast<const float4*>(s);
#pragma unroll
    for (int i = threadIdx.x; i < TPB * COUT / 4; i += TPB) o4[i] = s4[i];
}

extern "C" void kernel_launch(void* const* d_in, const int* in_sizes, int n_in,
                              void* d_out, int out_size) {
    const float* raw  = (const float*)d_in[0];
    const float* ext  = (const float*)d_in[1];
    const float* intr = (const float*)d_in[2];
    int v = in_sizes[1] / 16;           // extrinsics (b*v,4,4)
    prep_kernel<<<1, 32>>>(ext, intr, v);
    int total = v * HW_;                // 2,457,600 pixels, divisible by TPB
    splat_kernel<<<total / TPB, TPB>>>(raw, (float*)d_out);
}

// round 5
// speedup vs baseline: 1.3437x; 1.3437x over previous
#include <cuda_runtime.h>
#include <math.h>

#define W_    640
#define H_    480
#define HW_   (W_ * H_)
#define CIN   14
#define COUT  15
#define TPB   256
#define BLKS_PER_VIEW (HW_ / TPB)   // 1200

struct ViewConst {
    float M[9];   // inv(intrinsics)
    float R[9];   // extrinsics rotation
    float t[3];   // extrinsics translation
    float mult;   // sum(inv(intr[:2,:2]))
};

__device__ __forceinline__ float sigmoidf_(float x) {
    return __fdividef(1.0f, 1.0f + __expf(-x));
}
__device__ __forceinline__ float softplusf_(float x) {
    // stable log(1+exp(x)) with MUFU EX2/LG2
    float l = __logf(1.0f + __expf(-fabsf(x)));
    return x > 0.0f ? x + l : l;
}

__global__ __launch_bounds__(TPB) void splat_kernel(const float* __restrict__ raw,
                                                    const float* __restrict__ ext,
                                                    const float* __restrict__ intr,
                                                    float* __restrict__ out) {
    __shared__ float s[TPB * COUT];
    __shared__ ViewConst svc;

    int vi  = blockIdx.x / BLKS_PER_VIEW;
    int pix = (blockIdx.x - vi * BLKS_PER_VIEW) * TPB + threadIdx.x;
    int y   = pix / W_;
    int x   = pix - y * W_;

    // channel loads first: independent of the barrier, latency overlaps prep
    const float* base = raw + vi * (CIN * HW_) + pix;
    float ch[CIN];
#pragma unroll
    for (int c = 0; c < CIN; c++) ch[c] = __ldg(base + c * HW_);

    // per-view constants: one thread per block (L1-cached loads, ~60 flops)
    if (threadIdx.x == 0) {
        const float* K = intr + vi * 9;
        float a = K[0], b = K[1], c = K[2];
        float d = K[3], e = K[4], f = K[5];
        float g = K[6], h = K[7], k = K[8];
        float A = e * k - f * h;
        float B = f * g - d * k;
        float C = d * h - e * g;
        float inv = __fdividef(1.0f, a * A + b * B + c * C);
        svc.M[0] = A * inv;  svc.M[1] = (c * h - b * k) * inv;  svc.M[2] = (b * f - c * e) * inv;
        svc.M[3] = B * inv;  svc.M[4] = (a * k - c * g) * inv;  svc.M[5] = (c * d - a * f) * inv;
        svc.M[6] = C * inv;  svc.M[7] = (b * g - a * h) * inv;  svc.M[8] = (a * e - b * d) * inv;
        const float* E = ext + vi * 16;
#pragma unroll
        for (int r = 0; r < 3; r++) {
            svc.R[r * 3 + 0] = E[r * 4 + 0];
            svc.R[r * 3 + 1] = E[r * 4 + 1];
            svc.R[r * 3 + 2] = E[r * 4 + 2];
            svc.t[r]         = E[r * 4 + 3];
        }
        svc.mult = __fdividef(a + e - b - d, a * e - b * d);
    }
    __syncthreads();

    float R0 = svc.R[0], R1 = svc.R[1], R2 = svc.R[2];
    float R3 = svc.R[3], R4 = svc.R[4], R5 = svc.R[5];
    float R6 = svc.R[6], R7 = svc.R[7], R8 = svc.R[8];

    // pixel coords + sigmoid offset, unproject through inv(K)
    float cx = (float)x + sigmoidf_(ch[12]) - 0.5f;
    float cy = (float)y + sigmoidf_(ch[13]) - 0.5f;
    float dx = svc.M[0] * cx + svc.M[1] * cy + svc.M[2];
    float dy = svc.M[3] * cx + svc.M[4] * cy + svc.M[5];
    float dz = svc.M[6] * cx + svc.M[7] * cy + svc.M[8];
    float dn = rsqrtf(dx * dx + dy * dy + dz * dz);
    dx *= dn; dy *= dn; dz *= dn;

    // rotate to world (homogeneous w=0 -> rotation only)
    float wdx = R0 * dx + R1 * dy + R2 * dz;
    float wdy = R3 * dx + R4 * dy + R5 * dz;
    float wdz = R6 * dx + R7 * dy + R8 * dz;

    float disp  = sigmoidf_(ch[3]);
    float depth = __fdividef(1.0f, disp * (1.0f / 0.05f - 1.0f / 20.0f) + 1.0f / 20.0f);

    float mx = svc.t[0] + wdx * depth;
    float my = svc.t[1] + wdy * depth;
    float mz = svc.t[2] + wdz * depth;

    // quaternion (x,y,z,w) -> rotation matrix
    float qx = ch[8], qy = ch[9], qz = ch[10], qw = ch[11];
    float qn = rsqrtf(qx * qx + qy * qy + qz * qz + qw * qw);
    qx *= qn; qy *= qn; qz *= qn; qw *= qn;

    float c00 = 1.0f - 2.0f * (qy * qy + qz * qz);
    float c01 = 2.0f * (qx * qy - qz * qw);
    float c02 = 2.0f * (qx * qz + qy * qw);
    float c10 = 2.0f * (qx * qy + qz * qw);
    float c11 = 1.0f - 2.0f * (qx * qx + qz * qz);
    float c12 = 2.0f * (qy * qz - qx * qw);
    float c20 = 2.0f * (qx * qz - qy * qw);
    float c21 = 2.0f * (qy * qz + qx * qw);
    float c22 = 1.0f - 2.0f * (qx * qx + qy * qy);

    // m = R_ext * cam_m
    float m00 = R0 * c00 + R1 * c10 + R2 * c20;
    float m01 = R0 * c01 + R1 * c11 + R2 * c21;
    float m02 = R0 * c02 + R1 * c12 + R2 * c22;
    float m10 = R3 * c00 + R4 * c10 + R5 * c20;
    float m11 = R3 * c01 + R4 * c11 + R5 * c21;
    float m12 = R3 * c02 + R4 * c12 + R5 * c22;
    float m20 = R6 * c00 + R7 * c10 + R8 * c20;
    float m21 = R6 * c01 + R7 * c11 + R8 * c21;
    float m22 = R6 * c02 + R7 * c12 + R8 * c22;

    float tr = m00 + m11 + m22;
    // argmax([m00,m11,m22,tr]) with first-occurrence tie rule
    int choice = 0; float best = m00;
    if (m11 > best) { best = m11; choice = 1; }
    if (m22 > best) { best = m22; choice = 2; }
    if (tr  > best) {             choice = 3; }

    float q0, q1, q2, q3;
    if (choice == 0)      { q0 = m21 - m12; q1 = 1.0f + m00 - m11 - m22; q2 = m01 + m10; q3 = m02 + m20; }
    else if (choice == 1) { q0 = m02 - m20; q1 = m01 + m10; q2 = 1.0f + m11 - m00 - m22; q3 = m12 + m21; }
    else if (choice == 2) { q0 = m10 - m01; q1 = m02 + m20; q2 = m12 + m21; q3 = 1.0f + m22 - m00 - m11; }
    else                  { q0 = 1.0f + tr; q1 = m21 - m12; q2 = m02 - m20; q3 = m10 - m01; }
    float qrn = rsqrtf(q0 * q0 + q1 * q1 + q2 * q2 + q3 * q3);
    q0 *= qrn; q1 *= qrn; q2 *= qrn; q3 *= qrn;

    // stage 15 channels/pixel in smem (stride 15 is odd -> conflict-free)
    float mult = svc.mult;
    float* sp = s + threadIdx.x * COUT;
    sp[0]  = mx; sp[1] = my; sp[2] = mz; sp[3] = 1.0f;
    sp[4]  = softplusf_(ch[0]);
    sp[5]  = softplusf_(ch[1]);
    sp[6]  = softplusf_(ch[2]);
    sp[7]  = sigmoidf_(ch[4]);
    sp[8]  = softplusf_(ch[5]) * mult;
    sp[9]  = softplusf_(ch[6]) * mult;
    sp[10] = softplusf_(ch[7]) * mult;
    sp[11] = q0; sp[12] = q1; sp[13] = q2; sp[14] = q3;
    __syncthreads();

    // coalesced 16B-vector writeback: 256*15*4 = 15360 bytes, 16B aligned per block
    float4*       o4 = reinterpret_cast<float4*>(out + (size_t)blockIdx.x * (TPB * COUT));
    const float4* s4 = reinterpret_cast<const float4*>(s);
#pragma unroll
    for (int i = threadIdx.x; i < TPB * COUT / 4; i += TPB) o4[i] = s4[i];
}

extern "C" void kernel_launch(void* const* d_in, const int* in_sizes, int n_in,
                              void* d_out, int out_size) {
    const float* raw  = (const float*)d_in[0];
    const float* ext  = (const float*)d_in[1];
    const float* intr = (const float*)d_in[2];
    int v = in_sizes[1] / 16;                 // extrinsics (b*v,4,4) -> v = 8
    splat_kernel<<<v * BLKS_PER_VIEW, TPB>>>(raw, ext, intr, (float*)d_out);
}